// round 1
// baseline (speedup 1.0000x reference)
#include <cuda_runtime.h>
#include <cstdint>
#include <cstddef>

#define B_  256
#define C_  4
#define N_  64
#define F_  256
#define OC_ 8
#define OF_ 256

// Scratch (no allocations allowed): v = softmax-weighted neighbor sum, z = concat(h, x)
__device__ float g_v[B_ * C_ * F_];        // 1 MB
__device__ float g_z[B_ * 2 * C_ * F_];    // 2 MB

// ---------------------------------------------------------------------------
// Kernel 1: attention weights + v[b,c,f] = sum_n w[b,n] * neighbor[b,n,c,f]
// Also writes the x-half of z (channels 4..7).
// One block per batch sample, 512 threads.
// ---------------------------------------------------------------------------
__global__ __launch_bounds__(512) void k1_attn(
    const float* __restrict__ x, const float* __restrict__ nb,
    const float* __restrict__ Wa1, const float* __restrict__ Wa2)
{
    __shared__ float ws1[256], ws2[256];
    __shared__ float s2s[64], wsm[64];
    __shared__ float red[16];
    __shared__ float s1_sh;
    __shared__ float4 vpart[256];

    const int b = blockIdx.x;
    const int t = threadIdx.x;
    const int lane = t & 31, w = t >> 5;

    // column sums of the attention weight matrices (C=4 rows each)
    if (t < 256) {
        float a = 0.f, bb = 0.f;
        #pragma unroll
        for (int c = 0; c < 4; c++) { a += Wa1[c * 256 + t]; bb += Wa2[c * 256 + t]; }
        ws1[t] = a; ws2[t] = bb;
    }
    __syncthreads();

    // s1[b] = sum_f (sum_c x[b,c,f]) * ws1[f]; also copy x into z channels 4..7
    float p = 0.f;
    if (t < 256) {
        float xs = 0.f;
        #pragma unroll
        for (int c = 0; c < 4; c++) {
            float xv = x[(b * 4 + c) * 256 + t];
            g_z[b * 2048 + (4 + c) * 256 + t] = xv;
            xs += xv;
        }
        p = xs * ws1[t];
    }
    #pragma unroll
    for (int o = 16; o > 0; o >>= 1) p += __shfl_xor_sync(0xffffffffu, p, o);
    if (lane == 0) red[w] = p;
    __syncthreads();
    if (t == 0) {
        float s = 0.f;
        #pragma unroll
        for (int i = 0; i < 16; i++) s += red[i];
        s1_sh = s;
    }

    // s2[b,n] = sum_{c,f} neighbor[b,n,c,f] * ws2[f]; 16 warps x 4 neighbors
    const float* nbb = nb + (size_t)b * 65536;
    #pragma unroll
    for (int j = 0; j < 4; j++) {
        int n = w * 4 + j;
        const float4* np = (const float4*)(nbb + n * 1024);
        float acc = 0.f;
        #pragma unroll
        for (int it = 0; it < 8; it++) {
            float4 q = np[it * 32 + lane];
            int f = (it * 128 + lane * 4) & 255;   // (c,f) flattened; f-part only
            acc += q.x * ws2[f] + q.y * ws2[f + 1] + q.z * ws2[f + 2] + q.w * ws2[f + 3];
        }
        #pragma unroll
        for (int o = 16; o > 0; o >>= 1) acc += __shfl_xor_sync(0xffffffffu, acc, o);
        if (lane == 0) s2s[n] = acc;
    }
    __syncthreads();

    // softmax over the 64 neighbors (warp 0, two logits per lane)
    if (w == 0) {
        float s1v = s1_sh;
        float l0 = s1v * s2s[lane];
        float l1 = s1v * s2s[lane + 32];
        float m = fmaxf(l0, l1);
        #pragma unroll
        for (int o = 16; o > 0; o >>= 1) m = fmaxf(m, __shfl_xor_sync(0xffffffffu, m, o));
        float e0 = __expf(l0 - m), e1 = __expf(l1 - m);
        float s = e0 + e1;
        #pragma unroll
        for (int o = 16; o > 0; o >>= 1) s += __shfl_xor_sync(0xffffffffu, s, o);
        float inv = 1.f / s;
        wsm[lane] = e0 * inv;
        wsm[lane + 32] = e1 * inv;
    }
    __syncthreads();

    // v[b,c,f] = sum_n w[n] * neighbor[b,n,c,f]; each half of the block does 32 n's
    const int half = t >> 8, tt = t & 255;
    const float4* np2 = (const float4*)nbb;
    float4 acc = make_float4(0.f, 0.f, 0.f, 0.f);
    #pragma unroll 4
    for (int n = half * 32; n < half * 32 + 32; n++) {
        float wn = wsm[n];
        float4 q = np2[n * 256 + tt];
        acc.x += wn * q.x; acc.y += wn * q.y; acc.z += wn * q.z; acc.w += wn * q.w;
    }
    if (half == 1) vpart[tt] = acc;
    __syncthreads();
    if (half == 0) {
        float4 o = vpart[tt];
        acc.x += o.x; acc.y += o.y; acc.z += o.z; acc.w += o.w;
        ((float4*)(g_v + b * 1024))[tt] = acc;
    }
}

// ---------------------------------------------------------------------------
// Kernel 2: adj (rank-1 outer product, symmetrized, sgnroot, column-normalized)
// + fused h[b,c,x] = sum_y adj[x,y]*x[y] using symmetry of a[x,y].
// One block per (b,c) pair, thread t owns column y=t. adj recomputed twice
// on-the-fly (F*F tile = 256KB doesn't fit smem) — MUFU cost hides under the
// 256 MB DRAM write.
// ---------------------------------------------------------------------------
__global__ __launch_bounds__(256) void k2_adj(
    const float* __restrict__ x, float* __restrict__ adj)
{
    __shared__ float xs[256], vs[256], us[256];
    const int bc = blockIdx.x;
    const int t = threadIdx.x;
    xs[t] = x[bc * 256 + t];
    vs[t] = g_v[bc * 256 + t];
    __syncthreads();
    const float xt = xs[t], vt = vs[t];

    // pass 1: column denominator den[t] = sum_x |a[x,t]|
    float den = 0.f;
    #pragma unroll 8
    for (int i = 0; i < 256; i++) {
        float tv = xs[i] * vt + xt * vs[i];
        float a = sqrtf(fmaxf(fabsf(tv), 1e-8f));
        den += (tv == 0.f) ? 0.f : a;
    }
    const float id = 1.f / (den + 1e-7f);
    us[t] = xt * id;     // u[y] = x[y] / den[y]
    __syncthreads();

    // pass 2: write adj column t (coalesced across threads), accumulate h[t]
    float h = 0.f;
    float* arow = adj + (size_t)bc * 65536 + t;
    #pragma unroll 8
    for (int i = 0; i < 256; i++) {
        float tv = xs[i] * vt + xt * vs[i];
        float s = sqrtf(fmaxf(fabsf(tv), 1e-8f));
        float a = (tv == 0.f) ? 0.f : copysignf(s, tv);
        arow[(size_t)i * 256] = a * id;      // adj[x=i, y=t] = a / den[t]
        h = fmaf(a, us[i], h);               // h[t] += a[i,t] * x[i]/den[i]  (a symmetric)
    }
    g_z[(bc >> 2) * 2048 + (bc & 3) * 256 + t] = h;   // z channels 0..3
}

// ---------------------------------------------------------------------------
// Kernel 3: out[b,o] = sum_k z[b,k] * W_conv[o,k]   (M=256, N=2048, K=2048)
// 64x64x32 tiles, double-buffered smem, packed fp32 FFMA2 (fma.rn.f32x2).
// ---------------------------------------------------------------------------
__device__ __forceinline__ unsigned long long pack2f(float v) {
    unsigned long long r;
    asm("mov.b64 %0, {%1, %2};" : "=l"(r) : "f"(v), "f"(v));
    return r;
}
__device__ __forceinline__ void ffma2(unsigned long long& d,
                                      unsigned long long a, unsigned long long b) {
    asm("fma.rn.f32x2 %0, %1, %2, %0;" : "+l"(d) : "l"(a), "l"(b));
}

#define LDA 66   // 64 + 2 pad: keeps 8B alignment for float2 reads, 2-way STS conflict max

__global__ __launch_bounds__(256) void k3_gemm(
    const float* __restrict__ W, float* __restrict__ out)
{
    __shared__ float As[2][32 * LDA];
    __shared__ float Bs[2][32 * LDA];
    const int t = threadIdx.x;
    const int bn = blockIdx.x * 64, bm = blockIdx.y * 64;
    const int tx = t & 15, ty = t >> 4;
    const int kk = t & 31, grp = t >> 5;

    const float* Ag = g_z + (bm + grp * 8) * 2048 + kk;
    const float* Bg = W + (size_t)(bn + grp * 8) * 2048 + kk;

    float a_pf[8], b_pf[8];
    #pragma unroll
    for (int i = 0; i < 8; i++) { a_pf[i] = Ag[i * 2048]; b_pf[i] = Bg[i * 2048]; }

    unsigned long long acc[4][2];
    #pragma unroll
    for (int j = 0; j < 4; j++) { acc[j][0] = 0ull; acc[j][1] = 0ull; }

    int buf = 0;
    for (int kt = 0; kt < 64; kt++) {
        #pragma unroll
        for (int i = 0; i < 8; i++) {
            As[buf][kk * LDA + grp * 8 + i] = a_pf[i];   // transposed: As[k][m]
            Bs[buf][kk * LDA + grp * 8 + i] = b_pf[i];   // transposed: Bs[k][n]
        }
        __syncthreads();
        if (kt < 63) {
            const float* Ag2 = Ag + (kt + 1) * 32;
            const float* Bg2 = Bg + (kt + 1) * 32;
            #pragma unroll
            for (int i = 0; i < 8; i++) { a_pf[i] = Ag2[i * 2048]; b_pf[i] = Bg2[i * 2048]; }
        }
        #pragma unroll
        for (int k2 = 0; k2 < 32; k2++) {
            const float* ar = &As[buf][k2 * LDA + ty * 4];
            const float* br = &Bs[buf][k2 * LDA + tx * 4];
            unsigned long long B0 = *(const unsigned long long*)br;
            unsigned long long B1 = *(const unsigned long long*)(br + 2);
            #pragma unroll
            for (int j = 0; j < 4; j++) {
                unsigned long long A2 = pack2f(ar[j]);
                ffma2(acc[j][0], A2, B0);
                ffma2(acc[j][1], A2, B1);
            }
        }
        buf ^= 1;
        // one sync per iter is sufficient: the sync above (next iteration) orders
        // all readers of a buffer before its next overwrite
    }

    #pragma unroll
    for (int j = 0; j < 4; j++) {
        int row = bm + ty * 4 + j;
        float2* op = (float2*)(out + (size_t)row * 2048 + bn + tx * 4);
        op[0] = *(float2*)&acc[j][0];
        op[1] = *(float2*)&acc[j][1];
    }
}

// ---------------------------------------------------------------------------
// Launch: output layout = concat(out (B*OC*OF), adj (B*C*F*F)) in fp32.
// ---------------------------------------------------------------------------
extern "C" void kernel_launch(void* const* d_in, const int* in_sizes, int n_in,
                              void* d_out, int out_size)
{
    const float* x   = (const float*)d_in[0];
    const float* nb  = (const float*)d_in[1];
    const float* Wa1 = (const float*)d_in[2];
    const float* Wa2 = (const float*)d_in[3];
    const float* Wc  = (const float*)d_in[4];
    float* out = (float*)d_out;
    float* adj = out + (size_t)B_ * OC_ * OF_;

    k1_attn<<<B_, 512>>>(x, nb, Wa1, Wa2);
    k2_adj<<<B_ * C_, 256>>>(x, adj);
    k3_gemm<<<dim3(2048 / 64, 256 / 64), 256>>>(Wc, out);
}

// round 3
// speedup vs baseline: 1.1855x; 1.1855x over previous
#include <cuda_runtime.h>
#include <cstdint>
#include <cstddef>

#define B_  256
#define C_  4
#define N_  64
#define F_  256
#define OC_ 8
#define OF_ 256

// Scratch (no allocations allowed)
__device__ float g_z[B_ * 2 * C_ * F_];    // 2 MB : concat(h, x) rows for GEMM
__device__ float g_w[B_ * N_];             // softmax weights

__device__ __forceinline__ float sqrt_ap(float v) {
    float r; asm("sqrt.approx.f32 %0, %1;" : "=f"(r) : "f"(v)); return r;
}
__device__ __forceinline__ float rcp_ap(float v) {
    float r; asm("rcp.approx.f32 %0, %1;" : "=f"(r) : "f"(v)); return r;
}

// ---------------------------------------------------------------------------
// Kernel 1: attention logits + softmax weights; copy x into z channels 4..7.
// One block per batch sample, 256 threads. One DRAM pass over neighbor.
// ---------------------------------------------------------------------------
__global__ __launch_bounds__(256) void k1_attn(
    const float* __restrict__ x, const float* __restrict__ nb,
    const float* __restrict__ Wa1, const float* __restrict__ Wa2)
{
    __shared__ float ws2[256];
    __shared__ float s2s[64];
    __shared__ float red[8];

    const int b = blockIdx.x;
    const int t = threadIdx.x;
    const int lane = t & 31, w = t >> 5;

    // column sums of attention weight matrices (C=4 rows each)
    float w1 = Wa1[t] + Wa1[256 + t] + Wa1[512 + t] + Wa1[768 + t];
    ws2[t]   = Wa2[t] + Wa2[256 + t] + Wa2[512 + t] + Wa2[768 + t];

    // s1 partial + copy x into z channels 4..7
    float xs = 0.f;
    #pragma unroll
    for (int c = 0; c < 4; c++) {
        float xv = x[(b * 4 + c) * 256 + t];
        g_z[b * 2048 + (4 + c) * 256 + t] = xv;
        xs += xv;
    }
    float p = xs * w1;
    #pragma unroll
    for (int o = 16; o > 0; o >>= 1) p += __shfl_xor_sync(0xffffffffu, p, o);
    if (lane == 0) red[w] = p;
    __syncthreads();

    // s2[b,n] : warp w handles 8 neighbors
    const float* nbb = nb + (size_t)b * 65536;
    #pragma unroll
    for (int j = 0; j < 8; j++) {
        const int n = w * 8 + j;
        const float4* np = (const float4*)(nbb + n * 1024);
        float acc = 0.f;
        #pragma unroll
        for (int it = 0; it < 8; it++) {
            float4 q = np[it * 32 + lane];
            int f = (it * 128 + lane * 4) & 255;
            acc += q.x * ws2[f] + q.y * ws2[f + 1] + q.z * ws2[f + 2] + q.w * ws2[f + 3];
        }
        #pragma unroll
        for (int o = 16; o > 0; o >>= 1) acc += __shfl_xor_sync(0xffffffffu, acc, o);
        if (lane == 0) s2s[n] = acc;
    }
    __syncthreads();

    // softmax over 64 neighbors (warp 0, 2 logits/lane)
    if (w == 0) {
        // full s1 = sum of red[0..7]: each 8-lane group covers all 8 slots via xor
        float s1v = red[lane & 7];
        #pragma unroll
        for (int o = 4; o > 0; o >>= 1) s1v += __shfl_xor_sync(0xffffffffu, s1v, o);
        float l0 = s1v * s2s[lane];
        float l1 = s1v * s2s[lane + 32];
        float m = fmaxf(l0, l1);
        #pragma unroll
        for (int o = 16; o > 0; o >>= 1) m = fmaxf(m, __shfl_xor_sync(0xffffffffu, m, o));
        float e0 = __expf(l0 - m), e1 = __expf(l1 - m);
        float s = e0 + e1;
        #pragma unroll
        for (int o = 16; o > 0; o >>= 1) s += __shfl_xor_sync(0xffffffffu, s, o);
        float inv = 1.f / s;
        g_w[b * 64 + lane]      = e0 * inv;
        g_w[b * 64 + lane + 32] = e1 * inv;
    }
}

// ---------------------------------------------------------------------------
// Kernel 2: v (from L2-resident neighbor) + adj + fused h.
// One block per (b,c), 256 threads. Thread owns 4 consecutive columns and a
// 64-row stripe; STG.128 streaming stores; sqrt.approx / rcp.approx only.
// ---------------------------------------------------------------------------
__global__ __launch_bounds__(256) void k2_adj(
    const float* __restrict__ x, const float* __restrict__ nb,
    float* __restrict__ adj)
{
    __shared__ float xs[256], vs[256], us[256], idn[256];
    __shared__ float wsm[64];
    __shared__ float pden[4 * 256];

    const int bc = blockIdx.x;
    const int b = bc >> 2, c = bc & 3;
    const int t = threadIdx.x;

    if (t < 64) wsm[t] = g_w[b * 64 + t];
    xs[t] = x[bc * 256 + t];
    __syncthreads();

    // v[t] = sum_n w[n] * neighbor[b,n,c,t]   (reads mostly from L2)
    {
        const float* nbp = nb + ((size_t)b * 256 + c) * 256 + t;
        float acc = 0.f;
        #pragma unroll 8
        for (int n = 0; n < 64; n++) acc += wsm[n] * nbp[(size_t)n * 1024];
        vs[t] = acc;
    }
    __syncthreads();

    const int r = t >> 6, cg = t & 63;
    const int i0 = r * 64;
    float xc[4], vc[4];
    #pragma unroll
    for (int j = 0; j < 4; j++) { xc[j] = xs[4 * cg + j]; vc[j] = vs[4 * cg + j]; }

    // pass 1: partial column denominators over my 64-row stripe
    float d[4] = {0.f, 0.f, 0.f, 0.f};
    #pragma unroll 4
    for (int ii = 0; ii < 64; ii++) {
        const int i = i0 + ii;
        const float xi = xs[i], vi = vs[i];
        #pragma unroll
        for (int j = 0; j < 4; j++) {
            float tv = xi * vc[j] + xc[j] * vi;
            float s = sqrt_ap(fmaxf(fabsf(tv), 1e-8f));
            d[j] += (tv != 0.f) ? s : 0.f;
        }
    }
    #pragma unroll
    for (int j = 0; j < 4; j++) pden[r * 256 + 4 * cg + j] = d[j];
    __syncthreads();

    {
        float den = pden[t] + pden[256 + t] + pden[512 + t] + pden[768 + t];
        float id = rcp_ap(den + 1e-7f);
        idn[t] = id;
        us[t] = xs[t] * id;
    }
    __syncthreads();

    // pass 2: write adj (STG.128 streaming) + accumulate h via symmetry
    float ic[4];
    #pragma unroll
    for (int j = 0; j < 4; j++) ic[j] = idn[4 * cg + j];
    float h[4] = {0.f, 0.f, 0.f, 0.f};
    float* ap = adj + (size_t)bc * 65536 + 4 * cg;

    #pragma unroll 4
    for (int ii = 0; ii < 64; ii++) {
        const int i = i0 + ii;
        const float xi = xs[i], vi = vs[i], usi = us[i];
        float4 o;
        #pragma unroll
        for (int j = 0; j < 4; j++) {
            float tv = xi * vc[j] + xc[j] * vi;
            float s = sqrt_ap(fmaxf(fabsf(tv), 1e-8f));
            float a = (tv != 0.f) ? copysignf(s, tv) : 0.f;
            (&o.x)[j] = a * ic[j];
            h[j] = fmaf(a, usi, h[j]);
        }
        __stcs((float4*)(ap + (size_t)i * 256), o);
    }
    #pragma unroll
    for (int j = 0; j < 4; j++) pden[r * 256 + 4 * cg + j] = h[j];
    __syncthreads();

    float hs = pden[t] + pden[256 + t] + pden[512 + t] + pden[768 + t];
    g_z[b * 2048 + c * 256 + t] = hs;
}

// ---------------------------------------------------------------------------
// Kernel 3: out[b,o] = sum_k z[b,k] * W_conv[o,k]   (M=256, N=2048, K=2048)
// 64x64x32 tiles, double-buffered smem, packed fp32 FFMA2.
// Inner loop: 4 LDS.64 + 4 MOV + 8 FFMA2 = 16 instr = FFMA2-pipe budget.
// ---------------------------------------------------------------------------
__device__ __forceinline__ unsigned long long pack2f(float v) {
    unsigned long long r;
    asm("mov.b64 %0, {%1, %2};" : "=l"(r) : "f"(v), "f"(v));
    return r;
}
__device__ __forceinline__ void ffma2(unsigned long long& d,
                                      unsigned long long a, unsigned long long b) {
    asm("fma.rn.f32x2 %0, %1, %2, %0;" : "+l"(d) : "l"(a), "l"(b));
}

#define LDA 66

__global__ __launch_bounds__(256) void k3_gemm(
    const float* __restrict__ W, float* __restrict__ out)
{
    __shared__ float As[2][32 * LDA];
    __shared__ float Bs[2][32 * LDA];
    const int t = threadIdx.x;
    const int bn = blockIdx.x * 64, bm = blockIdx.y * 64;
    const int tx = t & 15, ty = t >> 4;
    const int kk = t & 31, grp = t >> 5;

    const float* Ag = g_z + (bm + grp * 8) * 2048 + kk;
    const float* Bg = W + (size_t)(bn + grp * 8) * 2048 + kk;

    float a_pf[8], b_pf[8];
    #pragma unroll
    for (int i = 0; i < 8; i++) { a_pf[i] = Ag[i * 2048]; b_pf[i] = Bg[i * 2048]; }

    unsigned long long acc[4][2];
    #pragma unroll
    for (int j = 0; j < 4; j++) { acc[j][0] = 0ull; acc[j][1] = 0ull; }

    int buf = 0;
    for (int kt = 0; kt < 64; kt++) {
        #pragma unroll
        for (int i = 0; i < 8; i++) {
            As[buf][kk * LDA + grp * 8 + i] = a_pf[i];
            Bs[buf][kk * LDA + grp * 8 + i] = b_pf[i];
        }
        __syncthreads();
        if (kt < 63) {
            const float* Ag2 = Ag + (kt + 1) * 32;
            const float* Bg2 = Bg + (kt + 1) * 32;
            #pragma unroll
            for (int i = 0; i < 8; i++) { a_pf[i] = Ag2[i * 2048]; b_pf[i] = Bg2[i * 2048]; }
        }
        #pragma unroll
        for (int k2 = 0; k2 < 32; k2++) {
            const float* ar = &As[buf][k2 * LDA + ty * 4];
            const float* br = &Bs[buf][k2 * LDA + tx * 4];
            float2 a01 = *(const float2*)ar;
            float2 a23 = *(const float2*)(ar + 2);
            unsigned long long B0 = *(const unsigned long long*)br;
            unsigned long long B1 = *(const unsigned long long*)(br + 2);
            unsigned long long A0 = pack2f(a01.x);
            unsigned long long A1 = pack2f(a01.y);
            unsigned long long A2 = pack2f(a23.x);
            unsigned long long A3 = pack2f(a23.y);
            ffma2(acc[0][0], A0, B0); ffma2(acc[0][1], A0, B1);
            ffma2(acc[1][0], A1, B0); ffma2(acc[1][1], A1, B1);
            ffma2(acc[2][0], A2, B0); ffma2(acc[2][1], A2, B1);
            ffma2(acc[3][0], A3, B0); ffma2(acc[3][1], A3, B1);
        }
        buf ^= 1;
    }

    #pragma unroll
    for (int j = 0; j < 4; j++) {
        int row = bm + ty * 4 + j;
        float2* op = (float2*)(out + (size_t)row * 2048 + bn + tx * 4);
        op[0] = *(float2*)&acc[j][0];
        op[1] = *(float2*)&acc[j][1];
    }
}

// ---------------------------------------------------------------------------
// Launch: output layout = concat(out (B*OC*OF), adj (B*C*F*F)) in fp32.
// ---------------------------------------------------------------------------
extern "C" void kernel_launch(void* const* d_in, const int* in_sizes, int n_in,
                              void* d_out, int out_size)
{
    const float* x   = (const float*)d_in[0];
    const float* nb  = (const float*)d_in[1];
    const float* Wa1 = (const float*)d_in[2];
    const float* Wa2 = (const float*)d_in[3];
    const float* Wc  = (const float*)d_in[4];
    float* out = (float*)d_out;
    float* adj = out + (size_t)B_ * OC_ * OF_;

    k1_attn<<<B_, 256>>>(x, nb, Wa1, Wa2);
    k2_adj<<<B_ * C_, 256>>>(x, nb, adj);
    k3_gemm<<<dim3(2048 / 64, 256 / 64), 256>>>(Wc, out);
}